// round 14
// baseline (speedup 1.0000x reference)
#include <cuda_runtime.h>
#include <math.h>

#define KSEL 16
#define TPB 256
#define GMAX 4096             // max supported grid (g_bmax sizing)
#define CAP 4096              // candidate capacity (expected ~600 survivors)
#define SLOTS (CAP / TPB)     // 16 shared-key slots per merge thread

#define NEG_BIG (-1.0e30f)
#define UMAX64(a,b) ((a) > (b) ? (a) : (b))

// Device scratch (zero-initialized at load; reset in-kernel for graph replay).
__device__ float g_bmax[GMAX];
__device__ volatile float g_thr;
__device__ int   g_cnt;
__device__ int   g_tick1;
__device__ int   g_tick2;
__device__ volatile int g_ready;
__device__ unsigned long long g_ck[CAP];   // packed (d2bits<<32)|(~idx)

__global__ void __launch_bounds__(TPB)
locse_fused(const float* __restrict__ P, const float* __restrict__ W,
            const float* __restrict__ bvec, const int* __restrict__ iptr,
            float* __restrict__ out, int N, int chunk)
{
    __shared__ unsigned long long skey[CAP];          // merge keys (last block only)
    __shared__ float sw[TPB / 32];
    __shared__ unsigned long long swk[TPB / 32];
    __shared__ unsigned long long s_win;
    __shared__ int  seli[KSEL];
    __shared__ int  s_last1, s_last2;

    const int tid  = threadIdx.x;
    const int bid  = blockIdx.x;
    const int grid = gridDim.x;

    const int i = *iptr;
    const float pix = __ldg(P + 6 * i + 0);
    const float piy = __ldg(P + 6 * i + 1);
    const float piz = __ldg(P + 6 * i + 2);

    // ---------------- Phase 1: sample 512 contiguous points per block -------
    {
        long long base = (long long)bid * chunk;      // chunk >= 512, disjoint
        float m = NEG_BIG;
#pragma unroll
        for (int s = 0; s < 2; s++) {
            long long pt = base + 2 * tid + s;
            float dx = __ldg(P + 6 * pt + 0) - pix;
            float dy = __ldg(P + 6 * pt + 1) - piy;
            float dz = __ldg(P + 6 * pt + 2) - piz;
            m = fmaxf(m, dx * dx + dy * dy + dz * dz);
        }
#pragma unroll
        for (int off = 16; off; off >>= 1)
            m = fmaxf(m, __shfl_xor_sync(0xffffffffu, m, off));
        if ((tid & 31) == 0) sw[tid >> 5] = m;
        __syncthreads();
        if (tid == 0) {
            float bm = sw[0];
#pragma unroll
            for (int w = 1; w < TPB / 32; w++) bm = fmaxf(bm, sw[w]);
            g_bmax[bid] = bm;
            __threadfence();
            s_last1 = (atomicAdd(&g_tick1, 1) == grid - 1);
        }
        __syncthreads();
    }

    if (s_last1) {
        // Threshold: 17th largest of 32 lane-group maxima (disjoint groups).
        if (tid < 32) {
            float m = NEG_BIG;
            for (int j = tid; j < grid; j += 32)
                m = fmaxf(m, ((volatile float*)g_bmax)[j]);
            float thr = NEG_BIG;
#pragma unroll 1
            for (int r = 0; r < 17; r++) {
                float w = m;
#pragma unroll
                for (int off = 16; off; off >>= 1)
                    w = fmaxf(w, __shfl_xor_sync(0xffffffffu, w, off));
                thr = w;
                if (m == w) m = NEG_BIG;
            }
            if (tid == 0) {
                unsigned tb = __float_as_uint(thr);   // thr >= 0
                tb = (tb >= 16u) ? tb - 16u : 0u;     // 16-ulp slack (rounding/ties)
                g_cnt = 0;
                g_thr = __uint_as_float(tb);
                __threadfence();
                atomicExch((int*)&g_ready, 1);
            }
        }
        __syncthreads();
    } else {
        if (tid == 0) { while (g_ready == 0) __nanosleep(64); }
        __syncthreads();
        __threadfence();
    }
    const float thr = g_thr;

    // ---------------- Phase 2: stream all points, push u64 keys -------------
    {
        const float4* __restrict__ P4 = (const float4*)P;
        const int stride = grid * TPB * 4;
        for (int p = (bid * TPB + tid) * 4; p < N; p += stride) {
            if (p + 3 < N) {
                const int q = (p >> 1) * 3;
                float4 a0 = P4[q + 0];
                float4 a1 = P4[q + 1];
                float4 a2 = P4[q + 2];
                float4 a3 = P4[q + 3];
                float4 a4 = P4[q + 4];
                float4 a5 = P4[q + 5];

                float d2a, d2b, d2c, d2d;
                { float dx = a0.x - pix, dy = a0.y - piy, dz = a0.z - piz; d2a = dx*dx + dy*dy + dz*dz; }
                { float dx = a1.z - pix, dy = a1.w - piy, dz = a2.x - piz; d2b = dx*dx + dy*dy + dz*dz; }
                { float dx = a3.x - pix, dy = a3.y - piy, dz = a3.z - piz; d2c = dx*dx + dy*dy + dz*dz; }
                { float dx = a4.z - pix, dy = a4.w - piy, dz = a5.x - piz; d2d = dx*dx + dy*dy + dz*dz; }

                if (d2a > thr) {
                    int pos = atomicAdd(&g_cnt, 1);
                    if (pos < CAP) g_ck[pos] = ((unsigned long long)__float_as_uint(d2a) << 32) | (0xFFFFFFFFu - (unsigned)p);
                }
                if (d2b > thr) {
                    int pos = atomicAdd(&g_cnt, 1);
                    if (pos < CAP) g_ck[pos] = ((unsigned long long)__float_as_uint(d2b) << 32) | (0xFFFFFFFFu - (unsigned)(p + 1));
                }
                if (d2c > thr) {
                    int pos = atomicAdd(&g_cnt, 1);
                    if (pos < CAP) g_ck[pos] = ((unsigned long long)__float_as_uint(d2c) << 32) | (0xFFFFFFFFu - (unsigned)(p + 2));
                }
                if (d2d > thr) {
                    int pos = atomicAdd(&g_cnt, 1);
                    if (pos < CAP) g_ck[pos] = ((unsigned long long)__float_as_uint(d2d) << 32) | (0xFFFFFFFFu - (unsigned)(p + 3));
                }
            } else {
                for (int t = p; t < N; t++) {
                    float dx = __ldg(P + 6 * t + 0) - pix;
                    float dy = __ldg(P + 6 * t + 1) - piy;
                    float dz = __ldg(P + 6 * t + 2) - piz;
                    float d2 = dx * dx + dy * dy + dz * dz;
                    if (d2 > thr) {
                        int pos = atomicAdd(&g_cnt, 1);
                        if (pos < CAP) g_ck[pos] = ((unsigned long long)__float_as_uint(d2) << 32) | (0xFFFFFFFFu - (unsigned)t);
                    }
                }
            }
        }
    }

    // ---------------- Phase 3: last block merges + writes output ------------
    if (tid == 0) {
        __threadfence();
        s_last2 = (atomicAdd(&g_tick2, 1) == grid - 1);
    }
    __syncthreads();
    if (!s_last2) return;

    int n = *(volatile int*)&g_cnt;
    if (n > CAP) n = CAP;

    for (int j = tid; j < CAP; j += TPB)
        skey[j] = (j < n) ? g_ck[j] : 0ull;
    __syncthreads();

#pragma unroll 1
    for (int sel = 0; sel < KSEL; sel++) {
        unsigned long long m = 0ull;
#pragma unroll
        for (int k = 0; k < SLOTS; k++)
            m = UMAX64(m, skey[tid + k * TPB]);
#pragma unroll
        for (int off = 16; off; off >>= 1) {
            unsigned long long o = __shfl_xor_sync(0xffffffffu, m, off);
            m = UMAX64(m, o);
        }
        if ((tid & 31) == 0) swk[tid >> 5] = m;
        __syncthreads();
        if (tid == 0) {
            unsigned long long w = swk[0];
#pragma unroll
            for (int q = 1; q < TPB / 32; q++) w = UMAX64(w, swk[q]);
            s_win = w;
            seli[sel] = (int)(0xFFFFFFFFu - (unsigned)(w & 0xFFFFFFFFull));
        }
        __syncthreads();
        const unsigned long long win = s_win;
#pragma unroll
        for (int k = 0; k < SLOTS; k++)
            if (skey[tid + k * TPB] == win) skey[tid + k * TPB] = 0ull;
        __syncthreads();
    }

    if (tid < KSEL) {
        const int k  = tid;
        const int ix = seli[k];
        const float nx = P[6 * ix + 0];
        const float ny = P[6 * ix + 1];
        const float nz = P[6 * ix + 2];
        const float dx = pix - nx, dy = piy - ny, dz = piz - nz;
        const float dist = sqrtf(dx * dx + dy * dy + dz * dz);

        float feat[10] = { pix, piy, piz, nx, ny, nz, dx, dy, dz, dist };

        out[k * 6 + 0] = nx;
        out[k * 6 + 1] = ny;
        out[k * 6 + 2] = nz;
#pragma unroll
        for (int j = 0; j < 3; j++) {
            float r = bvec[j];
#pragma unroll
            for (int f = 0; f < 10; f++) r += feat[f] * W[j * 10 + f];
            out[k * 6 + 3 + j] = r;
        }
    }

    // Reset for next graph replay.
    if (tid == 0) {
        g_tick1 = 0;
        g_tick2 = 0;
        atomicExch((int*)&g_ready, 0);
    }
}

// ---------------------------------------------------------------------------
extern "C" void kernel_launch(void* const* d_in, const int* in_sizes, int n_in,
                              void* d_out, int out_size)
{
    const float* P  = (const float*)d_in[0];
    const float* W  = (const float*)d_in[1];
    const float* bv = (const float*)d_in[2];
    const int*   ip = (const int*)d_in[3];
    float* out = (float*)d_out;

    const int N = in_sizes[0] / 6;     // 8,000,000 points

    // Size grid for guaranteed full residency (spin-wait safety).
    int dev = 0, nsm = 148, occ = 1;
    cudaGetDevice(&dev);
    cudaDeviceGetAttribute(&nsm, cudaDevAttrMultiProcessorCount, dev);
    cudaOccupancyMaxActiveBlocksPerMultiprocessor(&occ, locse_fused, TPB, 0);
    if (occ < 1) occ = 1;
    int grid = nsm * occ;
    if (grid > GMAX) grid = GMAX;
    if (grid > N / 512) grid = N / 512;   // keep sample chunks disjoint
    if (grid < 32) grid = 32;

    int chunk = N / grid;                 // >= 512

    locse_fused<<<grid, TPB>>>(P, W, bv, ip, out, N, chunk);
}